// round 2
// baseline (speedup 1.0000x reference)
#include <cuda_runtime.h>
#include <math.h>

#define Tn 2048
#define Hn 2048
#define Fn 512
#define En 64
#define Kn 8
#define Cn 320
#define F2n 1024
#define KTn (Kn*Tn)
#define NCHUNK 64
#define CHSZ 256

// ---------------- scratch (device globals; zero-initialized at load) ----------------
__device__ float g_logits[Tn*En];
__device__ int   g_topi[KTn];       // [k*T + t]
__device__ float g_topv[KTn];
__device__ float g_probsum[En];
__device__ int   g_chunkcnt[NCHUNK*En];
__device__ int   g_basecnt[NCHUNK*En];
__device__ int   g_cnt[En];         // capped counts (<= Cn)
__device__ int   g_totcnt[En];      // uncapped (for aux loss)
__device__ int   g_tok[En*Cn];
__device__ float g_wslot[En*Cn];
__device__ float g_hbuf[(size_t)En*Cn*Fn];   // 42 MB, relu(g)*u*w per expert slot
__device__ float g_hs[(size_t)Tn*2*F2n];     // 16 MB, shared-expert hidden

// ---------------- GEMM cores: BM=BN=64, BK=16, 256 threads, 4x4 per thread ----------
__device__ __forceinline__ void gemm1_core(
    const float* const* __restrict__ Arows,
    const float* __restrict__ B, int ldB, int Kd, int n0,
    float acc[16], float* As, float* Bs)
{
    int tid = threadIdx.x;
    int tx = tid & 15, ty = tid >> 4;
    int lmA = tid >> 2, lkA = (tid & 3) << 2;
    int lkB = tid >> 4, lnB = (tid & 15) << 2;
    const float* Bp = B + (size_t)lkB * ldB + n0 + lnB;
    for (int k0 = 0; k0 < Kd; k0 += 16) {
        float4 av = *(const float4*)(Arows[lmA] + k0 + lkA);
        float4 bv = *(const float4*)(Bp);
        Bp += (size_t)16 * ldB;
        *(float4*)(As + lmA*16 + lkA) = av;
        *(float4*)(Bs + lkB*64 + lnB) = bv;
        __syncthreads();
#pragma unroll
        for (int kk = 0; kk < 16; kk++) {
            float4 b = *(const float4*)(Bs + kk*64 + (tx<<2));
#pragma unroll
            for (int i = 0; i < 4; i++) {
                float a = As[(ty*4+i)*16 + kk];
                acc[i*4+0] += a*b.x; acc[i*4+1] += a*b.y;
                acc[i*4+2] += a*b.z; acc[i*4+3] += a*b.w;
            }
        }
        __syncthreads();
    }
}

__device__ __forceinline__ void gemm2_core(
    const float* const* __restrict__ Arows,
    const float* __restrict__ Bg, const float* __restrict__ Bu,
    int ldB, int Kd, int n0,
    float accg[16], float accu[16], float* As, float* Bgs, float* Bus)
{
    int tid = threadIdx.x;
    int tx = tid & 15, ty = tid >> 4;
    int lmA = tid >> 2, lkA = (tid & 3) << 2;
    int lkB = tid >> 4, lnB = (tid & 15) << 2;
    const float* Bgp = Bg + (size_t)lkB * ldB + n0 + lnB;
    const float* Bup = Bu + (size_t)lkB * ldB + n0 + lnB;
    for (int k0 = 0; k0 < Kd; k0 += 16) {
        float4 av  = *(const float4*)(Arows[lmA] + k0 + lkA);
        float4 bgv = *(const float4*)(Bgp);
        float4 buv = *(const float4*)(Bup);
        Bgp += (size_t)16 * ldB;
        Bup += (size_t)16 * ldB;
        *(float4*)(As  + lmA*16 + lkA) = av;
        *(float4*)(Bgs + lkB*64 + lnB) = bgv;
        *(float4*)(Bus + lkB*64 + lnB) = buv;
        __syncthreads();
#pragma unroll
        for (int kk = 0; kk < 16; kk++) {
            float4 bg = *(const float4*)(Bgs + kk*64 + (tx<<2));
            float4 bu = *(const float4*)(Bus + kk*64 + (tx<<2));
#pragma unroll
            for (int i = 0; i < 4; i++) {
                float a = As[(ty*4+i)*16 + kk];
                accg[i*4+0] += a*bg.x; accg[i*4+1] += a*bg.y;
                accg[i*4+2] += a*bg.z; accg[i*4+3] += a*bg.w;
                accu[i*4+0] += a*bu.x; accu[i*4+1] += a*bu.y;
                accu[i*4+2] += a*bu.z; accu[i*4+3] += a*bu.w;
            }
        }
        __syncthreads();
    }
}

// ---------------- small kernels ----------------
__global__ void zero_kernel() {
    if (threadIdx.x < En) g_probsum[threadIdx.x] = 0.f;
}

// logits = x @ router_w : M=T, N=E(=64), K=H
__global__ __launch_bounds__(256) void logits_kernel(
    const float* __restrict__ x, const float* __restrict__ rw)
{
    __shared__ float As[64*16];
    __shared__ float Bs[16*64];
    __shared__ const float* Arows[64];
    int tid = threadIdx.x;
    int m0 = blockIdx.y * 64, n0 = blockIdx.x * 64;
    if (tid < 64) Arows[tid] = x + (size_t)(m0 + tid) * Hn;
    __syncthreads();
    float acc[16] = {};
    gemm1_core(Arows, rw, En, Hn, n0, acc, As, Bs);
    int tx = tid & 15, ty = tid >> 4;
#pragma unroll
    for (int i = 0; i < 4; i++) {
        float4 r = make_float4(acc[i*4+0], acc[i*4+1], acc[i*4+2], acc[i*4+3]);
        *(float4*)(g_logits + (size_t)(m0 + ty*4 + i)*En + n0 + (tx<<2)) = r;
    }
}

// per-token softmax + top-8 + probsum accumulation
__global__ void router_post_kernel() {
    int t = blockIdx.x, tid = threadIdx.x;   // 64 threads
    __shared__ float sp[En];
    __shared__ float red[En];
    float l = g_logits[t*En + tid];
    red[tid] = l; __syncthreads();
    for (int s = 32; s > 0; s >>= 1) {
        if (tid < s) red[tid] = fmaxf(red[tid], red[tid+s]);
        __syncthreads();
    }
    float mx = red[0]; __syncthreads();
    float ex = expf(l - mx);
    red[tid] = ex; __syncthreads();
    for (int s = 32; s > 0; s >>= 1) {
        if (tid < s) red[tid] += red[tid+s];
        __syncthreads();
    }
    float p = ex / red[0];
    sp[tid] = p;
    atomicAdd(&g_probsum[tid], p);
    __syncthreads();
    if (tid == 0) {
        // stable top-8: strict > keeps lowest index on ties (matches lax.top_k)
        for (int k = 0; k < Kn; k++) {
            float bv = -1.f; int bi = 0;
            for (int e = 0; e < En; e++) {
                float v = sp[e];
                if (v > bv) { bv = v; bi = e; }
            }
            g_topi[k*Tn + t] = bi;
            g_topv[k*Tn + t] = bv;
            sp[bi] = -1.f;
        }
    }
}

__global__ void hist_kernel() {
    __shared__ int cnt[En];
    int tid = threadIdx.x;
    if (tid < En) cnt[tid] = 0;
    __syncthreads();
    int a = blockIdx.x * CHSZ + tid;
    int e = g_topi[a];
    atomicAdd(&cnt[e], 1);
    __syncthreads();
    if (tid < En) g_chunkcnt[blockIdx.x*En + tid] = cnt[tid];
}

__global__ void scan_kernel() {
    int e = threadIdx.x;   // 64 threads
    int run = 0;
    for (int c = 0; c < NCHUNK; c++) {
        g_basecnt[c*En + e] = run;
        run += g_chunkcnt[c*En + e];
    }
    g_totcnt[e] = run;
    g_cnt[e] = run < Cn ? run : Cn;
}

__global__ void pos_kernel() {
    __shared__ int se[CHSZ];
    int tid = threadIdx.x;
    int a = blockIdx.x * CHSZ + tid;
    int e = g_topi[a];
    se[tid] = e;
    __syncthreads();
    int rank = 0;
    for (int j = 0; j < tid; j++) rank += (se[j] == e);
    int slot = g_basecnt[blockIdx.x*En + e] + rank;
    if (slot < Cn) {
        int t = a & (Tn - 1);          // a = k*T + t
        g_tok[e*Cn + slot] = t;
        g_wslot[e*Cn + slot] = g_topv[a];
    }
}

// ---------------- shared experts ----------------
__global__ __launch_bounds__(256) void shared_gu_kernel(
    const float* __restrict__ x,
    const float* __restrict__ swg, const float* __restrict__ swu)
{
    __shared__ float As[64*16];
    __shared__ float Bgs[16*64];
    __shared__ float Bus[16*64];
    __shared__ const float* Arows[64];
    int tid = threadIdx.x;
    int e = blockIdx.z;
    int m0 = blockIdx.y * 64, n0 = blockIdx.x * 64;
    if (tid < 64) Arows[tid] = x + (size_t)(m0 + tid) * Hn;
    __syncthreads();
    float accg[16] = {}, accu[16] = {};
    gemm2_core(Arows, swg + (size_t)e*Hn*F2n, swu + (size_t)e*Hn*F2n,
               F2n, Hn, n0, accg, accu, As, Bgs, Bus);
    int tx = tid & 15, ty = tid >> 4;
#pragma unroll
    for (int i = 0; i < 4; i++) {
        int m = m0 + ty*4 + i;
        float4 r;
        r.x = fmaxf(accg[i*4+0], 0.f) * accu[i*4+0];
        r.y = fmaxf(accg[i*4+1], 0.f) * accu[i*4+1];
        r.z = fmaxf(accg[i*4+2], 0.f) * accu[i*4+2];
        r.w = fmaxf(accg[i*4+3], 0.f) * accu[i*4+3];
        *(float4*)(g_hs + (size_t)m*(2*F2n) + (size_t)e*F2n + n0 + (tx<<2)) = r;
    }
}

// out = hs @ swd_flat : M=T, N=H, K=2F2 ; plain store (initializes out)
__global__ __launch_bounds__(256) void shared_down_kernel(
    const float* __restrict__ swd, float* __restrict__ out)
{
    __shared__ float As[64*16];
    __shared__ float Bs[16*64];
    __shared__ const float* Arows[64];
    int tid = threadIdx.x;
    int m0 = blockIdx.y * 64, n0 = blockIdx.x * 64;
    if (tid < 64) Arows[tid] = g_hs + (size_t)(m0 + tid) * (2*F2n);
    __syncthreads();
    float acc[16] = {};
    gemm1_core(Arows, swd, Hn, 2*F2n, n0, acc, As, Bs);
    int tx = tid & 15, ty = tid >> 4;
#pragma unroll
    for (int i = 0; i < 4; i++) {
        int m = m0 + ty*4 + i;
        float4 r = make_float4(acc[i*4+0], acc[i*4+1], acc[i*4+2], acc[i*4+3]);
        *(float4*)(out + (size_t)m*Hn + n0 + (tx<<2)) = r;
    }
}

// ---------------- expert FFN ----------------
__global__ __launch_bounds__(256) void expert_gu_kernel(
    const float* __restrict__ x,
    const float* __restrict__ wg, const float* __restrict__ wu)
{
    int e = blockIdx.z;
    int cnt = g_cnt[e];
    int m0 = blockIdx.y * 64;
    if (m0 >= cnt) return;
    int n0 = blockIdx.x * 64;
    __shared__ float As[64*16];
    __shared__ float Bgs[16*64];
    __shared__ float Bus[16*64];
    __shared__ const float* Arows[64];
    __shared__ float sw[64];
    int tid = threadIdx.x;
    if (tid < 64) {
        int m = m0 + tid;
        int tk = (m < cnt) ? g_tok[e*Cn + m] : 0;
        Arows[tid] = x + (size_t)tk * Hn;
        sw[tid] = (m < cnt) ? g_wslot[e*Cn + m] : 0.f;
    }
    __syncthreads();
    float accg[16] = {}, accu[16] = {};
    gemm2_core(Arows, wg + (size_t)e*Hn*Fn, wu + (size_t)e*Hn*Fn,
               Fn, Hn, n0, accg, accu, As, Bgs, Bus);
    int tx = tid & 15, ty = tid >> 4;
#pragma unroll
    for (int i = 0; i < 4; i++) {
        int row = m0 + ty*4 + i;
        if (row < cnt) {
            float w = sw[ty*4 + i];
            float4 r;
            r.x = fmaxf(accg[i*4+0], 0.f) * accu[i*4+0] * w;
            r.y = fmaxf(accg[i*4+1], 0.f) * accu[i*4+1] * w;
            r.z = fmaxf(accg[i*4+2], 0.f) * accu[i*4+2] * w;
            r.w = fmaxf(accg[i*4+3], 0.f) * accu[i*4+3] * w;
            *(float4*)(g_hbuf + ((size_t)e*Cn + row)*Fn + n0 + (tx<<2)) = r;
        }
    }
}

__global__ __launch_bounds__(256) void expert_down_kernel(
    const float* __restrict__ wd, float* __restrict__ out)
{
    int e = blockIdx.z;
    int cnt = g_cnt[e];
    int m0 = blockIdx.y * 64;
    if (m0 >= cnt) return;
    int n0 = blockIdx.x * 64;
    __shared__ float As[64*16];
    __shared__ float Bs[16*64];
    __shared__ const float* Arows[64];
    __shared__ int stok[64];
    int tid = threadIdx.x;
    if (tid < 64) {
        int m = m0 + tid;
        stok[tid] = (m < cnt) ? g_tok[e*Cn + m] : 0;
        Arows[tid] = g_hbuf + ((size_t)e*Cn + m) * Fn;  // rows >= cnt are zeros
    }
    __syncthreads();
    float acc[16] = {};
    gemm1_core(Arows, wd + (size_t)e*Fn*Hn, Hn, Fn, n0, acc, As, Bs);
    int tx = tid & 15, ty = tid >> 4;
#pragma unroll
    for (int i = 0; i < 4; i++) {
        int row = m0 + ty*4 + i;
        if (row < cnt) {
            float* op = out + (size_t)stok[ty*4+i]*Hn + n0 + (tx<<2);
            atomicAdd(op + 0, acc[i*4+0]);
            atomicAdd(op + 1, acc[i*4+1]);
            atomicAdd(op + 2, acc[i*4+2]);
            atomicAdd(op + 3, acc[i*4+3]);
        }
    }
}

__global__ void aux_kernel(float* __restrict__ out, int write_aux) {
    __shared__ float red[En];
    int e = threadIdx.x;  // 64 threads
    red[e] = (float)g_totcnt[e] * g_probsum[e];
    __syncthreads();
    for (int s = 32; s > 0; s >>= 1) {
        if (e < s) red[e] += red[e+s];
        __syncthreads();
    }
    if (e == 0 && write_aux) {
        // aux = E * sum_e (totcnt/(T*K)) * (probsum/T)
        out[(size_t)Tn*Hn] = (float)En * red[0] / ((float)Tn * (float)Kn * (float)Tn);
    }
}

// ---------------- launch ----------------
extern "C" void kernel_launch(void* const* d_in, const int* in_sizes, int n_in,
                              void* d_out, int out_size) {
    const float* x   = (const float*)d_in[0];
    const float* rw  = (const float*)d_in[1];
    const float* wg  = (const float*)d_in[2];
    const float* wu  = (const float*)d_in[3];
    const float* wd  = (const float*)d_in[4];
    const float* swg = (const float*)d_in[5];
    const float* swu = (const float*)d_in[6];
    const float* swd = (const float*)d_in[7];
    float* out = (float*)d_out;

    zero_kernel<<<1, 64>>>();
    logits_kernel<<<dim3(En/64, Tn/64), 256>>>(x, rw);
    router_post_kernel<<<Tn, 64>>>();
    hist_kernel<<<NCHUNK, CHSZ>>>();
    scan_kernel<<<1, En>>>();
    pos_kernel<<<NCHUNK, CHSZ>>>();

    shared_gu_kernel<<<dim3(F2n/64, Tn/64, 2), 256>>>(x, swg, swu);
    shared_down_kernel<<<dim3(Hn/64, Tn/64), 256>>>(swd, out);

    expert_gu_kernel<<<dim3(Fn/64, (Cn+63)/64, En), 256>>>(x, wg, wu);
    expert_down_kernel<<<dim3(Hn/64, (Cn+63)/64, En), 256>>>(wd, out);

    int write_aux = (out_size > Tn*Hn) ? 1 : 0;
    aux_kernel<<<1, En>>>(out, write_aux);
}

// round 3
// speedup vs baseline: 1.0539x; 1.0539x over previous
#include <cuda_runtime.h>
#include <math.h>

#define Tn 2048
#define Hn 2048
#define Fn 512
#define En 64
#define Kn 8
#define Cn 320
#define F2n 1024
#define KTn (Kn*Tn)
#define NCHUNK 64
#define CHSZ 256

// ---------------- scratch (device globals; zero-initialized at load) ----------------
__device__ float g_logits[Tn*En];
__device__ int   g_topi[KTn];       // [k*T + t]
__device__ float g_topv[KTn];
__device__ float g_probsum[En];
__device__ int   g_chunkcnt[NCHUNK*En];
__device__ int   g_basecnt[NCHUNK*En];
__device__ int   g_cnt[En];         // capped counts (<= Cn)
__device__ int   g_totcnt[En];      // uncapped (for aux loss)
__device__ int   g_tok[En*Cn];
__device__ float g_wslot[En*Cn];
__device__ float g_hbuf[(size_t)En*Cn*Fn];   // 42 MB, relu(g)*u*w per expert slot
__device__ float g_hs[(size_t)Tn*2*F2n];     // 16 MB, shared-expert hidden

// ---------------- GEMM cores: BM=BN=64, BK=16, 256 threads, 4x4 per thread ----------
__device__ __forceinline__ void gemm1_core(
    const float* const* __restrict__ Arows,
    const float* __restrict__ B, int ldB, int Kd, int n0,
    float acc[16], float* As, float* Bs)
{
    int tid = threadIdx.x;
    int tx = tid & 15, ty = tid >> 4;
    int lmA = tid >> 2, lkA = (tid & 3) << 2;
    int lkB = tid >> 4, lnB = (tid & 15) << 2;
    const float* Bp = B + (size_t)lkB * ldB + n0 + lnB;
    for (int k0 = 0; k0 < Kd; k0 += 16) {
        float4 av = *(const float4*)(Arows[lmA] + k0 + lkA);
        float4 bv = *(const float4*)(Bp);
        Bp += (size_t)16 * ldB;
        *(float4*)(As + lmA*16 + lkA) = av;
        *(float4*)(Bs + lkB*64 + lnB) = bv;
        __syncthreads();
#pragma unroll
        for (int kk = 0; kk < 16; kk++) {
            float4 b = *(const float4*)(Bs + kk*64 + (tx<<2));
#pragma unroll
            for (int i = 0; i < 4; i++) {
                float a = As[(ty*4+i)*16 + kk];
                acc[i*4+0] += a*b.x; acc[i*4+1] += a*b.y;
                acc[i*4+2] += a*b.z; acc[i*4+3] += a*b.w;
            }
        }
        __syncthreads();
    }
}

__device__ __forceinline__ void gemm2_core(
    const float* const* __restrict__ Arows,
    const float* __restrict__ Bg, const float* __restrict__ Bu,
    int ldB, int Kd, int n0,
    float accg[16], float accu[16], float* As, float* Bgs, float* Bus)
{
    int tid = threadIdx.x;
    int tx = tid & 15, ty = tid >> 4;
    int lmA = tid >> 2, lkA = (tid & 3) << 2;
    int lkB = tid >> 4, lnB = (tid & 15) << 2;
    const float* Bgp = Bg + (size_t)lkB * ldB + n0 + lnB;
    const float* Bup = Bu + (size_t)lkB * ldB + n0 + lnB;
    for (int k0 = 0; k0 < Kd; k0 += 16) {
        float4 av  = *(const float4*)(Arows[lmA] + k0 + lkA);
        float4 bgv = *(const float4*)(Bgp);
        float4 buv = *(const float4*)(Bup);
        Bgp += (size_t)16 * ldB;
        Bup += (size_t)16 * ldB;
        *(float4*)(As  + lmA*16 + lkA) = av;
        *(float4*)(Bgs + lkB*64 + lnB) = bgv;
        *(float4*)(Bus + lkB*64 + lnB) = buv;
        __syncthreads();
#pragma unroll
        for (int kk = 0; kk < 16; kk++) {
            float4 bg = *(const float4*)(Bgs + kk*64 + (tx<<2));
            float4 bu = *(const float4*)(Bus + kk*64 + (tx<<2));
#pragma unroll
            for (int i = 0; i < 4; i++) {
                float a = As[(ty*4+i)*16 + kk];
                accg[i*4+0] += a*bg.x; accg[i*4+1] += a*bg.y;
                accg[i*4+2] += a*bg.z; accg[i*4+3] += a*bg.w;
                accu[i*4+0] += a*bu.x; accu[i*4+1] += a*bu.y;
                accu[i*4+2] += a*bu.z; accu[i*4+3] += a*bu.w;
            }
        }
        __syncthreads();
    }
}

// ---------------- small kernels ----------------
__global__ void zero_kernel() {
    if (threadIdx.x < En) g_probsum[threadIdx.x] = 0.f;
}

// logits = x @ router_w : M=T, N=E(=64), K=H
__global__ __launch_bounds__(256) void logits_kernel(
    const float* __restrict__ x, const float* __restrict__ rw)
{
    __shared__ float As[64*16];
    __shared__ float Bs[16*64];
    __shared__ const float* Arows[64];
    int tid = threadIdx.x;
    int m0 = blockIdx.y * 64, n0 = blockIdx.x * 64;
    if (tid < 64) Arows[tid] = x + (size_t)(m0 + tid) * Hn;
    __syncthreads();
    float acc[16] = {};
    gemm1_core(Arows, rw, En, Hn, n0, acc, As, Bs);
    int tx = tid & 15, ty = tid >> 4;
#pragma unroll
    for (int i = 0; i < 4; i++) {
        float4 r = make_float4(acc[i*4+0], acc[i*4+1], acc[i*4+2], acc[i*4+3]);
        *(float4*)(g_logits + (size_t)(m0 + ty*4 + i)*En + n0 + (tx<<2)) = r;
    }
}

// per-token softmax + top-8 + probsum accumulation
__global__ void router_post_kernel() {
    int t = blockIdx.x, tid = threadIdx.x;   // 64 threads
    __shared__ float sp[En];
    __shared__ float red[En];
    float l = g_logits[t*En + tid];
    red[tid] = l; __syncthreads();
    for (int s = 32; s > 0; s >>= 1) {
        if (tid < s) red[tid] = fmaxf(red[tid], red[tid+s]);
        __syncthreads();
    }
    float mx = red[0]; __syncthreads();
    float ex = expf(l - mx);
    red[tid] = ex; __syncthreads();
    for (int s = 32; s > 0; s >>= 1) {
        if (tid < s) red[tid] += red[tid+s];
        __syncthreads();
    }
    float p = ex / red[0];
    sp[tid] = p;
    atomicAdd(&g_probsum[tid], p);
    __syncthreads();
    if (tid == 0) {
        // stable top-8: strict > keeps lowest index on ties (matches lax.top_k)
        for (int k = 0; k < Kn; k++) {
            float bv = -1.f; int bi = 0;
            for (int e = 0; e < En; e++) {
                float v = sp[e];
                if (v > bv) { bv = v; bi = e; }
            }
            g_topi[k*Tn + t] = bi;
            g_topv[k*Tn + t] = bv;
            sp[bi] = -1.f;
        }
    }
}

__global__ void hist_kernel() {
    __shared__ int cnt[En];
    int tid = threadIdx.x;
    if (tid < En) cnt[tid] = 0;
    __syncthreads();
    int a = blockIdx.x * CHSZ + tid;
    int e = g_topi[a];
    atomicAdd(&cnt[e], 1);
    __syncthreads();
    if (tid < En) g_chunkcnt[blockIdx.x*En + tid] = cnt[tid];
}

__global__ void scan_kernel() {
    int e = threadIdx.x;   // 64 threads
    int run = 0;
    for (int c = 0; c < NCHUNK; c++) {
        g_basecnt[c*En + e] = run;
        run += g_chunkcnt[c*En + e];
    }
    g_totcnt[e] = run;
    g_cnt[e] = run < Cn ? run : Cn;
}

__global__ void pos_kernel() {
    __shared__ int se[CHSZ];
    int tid = threadIdx.x;
    int a = blockIdx.x * CHSZ + tid;
    int e = g_topi[a];
    se[tid] = e;
    __syncthreads();
    int rank = 0;
    for (int j = 0; j < tid; j++) rank += (se[j] == e);
    int slot = g_basecnt[blockIdx.x*En + e] + rank;
    if (slot < Cn) {
        int t = a & (Tn - 1);          // a = k*T + t
        g_tok[e*Cn + slot] = t;
        g_wslot[e*Cn + slot] = g_topv[a];
    }
}

// ---------------- shared experts ----------------
__global__ __launch_bounds__(256) void shared_gu_kernel(
    const float* __restrict__ x,
    const float* __restrict__ swg, const float* __restrict__ swu)
{
    __shared__ float As[64*16];
    __shared__ float Bgs[16*64];
    __shared__ float Bus[16*64];
    __shared__ const float* Arows[64];
    int tid = threadIdx.x;
    int e = blockIdx.z;
    int m0 = blockIdx.y * 64, n0 = blockIdx.x * 64;
    if (tid < 64) Arows[tid] = x + (size_t)(m0 + tid) * Hn;
    __syncthreads();
    float accg[16] = {}, accu[16] = {};
    gemm2_core(Arows, swg + (size_t)e*Hn*F2n, swu + (size_t)e*Hn*F2n,
               F2n, Hn, n0, accg, accu, As, Bgs, Bus);
    int tx = tid & 15, ty = tid >> 4;
#pragma unroll
    for (int i = 0; i < 4; i++) {
        int m = m0 + ty*4 + i;
        float4 r;
        r.x = fmaxf(accg[i*4+0], 0.f) * accu[i*4+0];
        r.y = fmaxf(accg[i*4+1], 0.f) * accu[i*4+1];
        r.z = fmaxf(accg[i*4+2], 0.f) * accu[i*4+2];
        r.w = fmaxf(accg[i*4+3], 0.f) * accu[i*4+3];
        *(float4*)(g_hs + (size_t)m*(2*F2n) + (size_t)e*F2n + n0 + (tx<<2)) = r;
    }
}

// out = hs @ swd_flat : M=T, N=H, K=2F2 ; plain store (initializes out)
__global__ __launch_bounds__(256) void shared_down_kernel(
    const float* __restrict__ swd, float* __restrict__ out)
{
    __shared__ float As[64*16];
    __shared__ float Bs[16*64];
    __shared__ const float* Arows[64];
    int tid = threadIdx.x;
    int m0 = blockIdx.y * 64, n0 = blockIdx.x * 64;
    if (tid < 64) Arows[tid] = g_hs + (size_t)(m0 + tid) * (2*F2n);
    __syncthreads();
    float acc[16] = {};
    gemm1_core(Arows, swd, Hn, 2*F2n, n0, acc, As, Bs);
    int tx = tid & 15, ty = tid >> 4;
#pragma unroll
    for (int i = 0; i < 4; i++) {
        int m = m0 + ty*4 + i;
        float4 r = make_float4(acc[i*4+0], acc[i*4+1], acc[i*4+2], acc[i*4+3]);
        *(float4*)(out + (size_t)m*Hn + n0 + (tx<<2)) = r;
    }
}

// ---------------- expert FFN ----------------
__global__ __launch_bounds__(256) void expert_gu_kernel(
    const float* __restrict__ x,
    const float* __restrict__ wg, const float* __restrict__ wu)
{
    int e = blockIdx.z;
    int cnt = g_cnt[e];
    int m0 = blockIdx.y * 64;
    if (m0 >= cnt) return;
    int n0 = blockIdx.x * 64;
    __shared__ float As[64*16];
    __shared__ float Bgs[16*64];
    __shared__ float Bus[16*64];
    __shared__ const float* Arows[64];
    __shared__ float sw[64];
    int tid = threadIdx.x;
    if (tid < 64) {
        int m = m0 + tid;
        int tk = (m < cnt) ? g_tok[e*Cn + m] : 0;
        Arows[tid] = x + (size_t)tk * Hn;
        sw[tid] = (m < cnt) ? g_wslot[e*Cn + m] : 0.f;
    }
    __syncthreads();
    float accg[16] = {}, accu[16] = {};
    gemm2_core(Arows, wg + (size_t)e*Hn*Fn, wu + (size_t)e*Hn*Fn,
               Fn, Hn, n0, accg, accu, As, Bgs, Bus);
    int tx = tid & 15, ty = tid >> 4;
#pragma unroll
    for (int i = 0; i < 4; i++) {
        int row = m0 + ty*4 + i;
        if (row < cnt) {
            float w = sw[ty*4 + i];
            float4 r;
            r.x = fmaxf(accg[i*4+0], 0.f) * accu[i*4+0] * w;
            r.y = fmaxf(accg[i*4+1], 0.f) * accu[i*4+1] * w;
            r.z = fmaxf(accg[i*4+2], 0.f) * accu[i*4+2] * w;
            r.w = fmaxf(accg[i*4+3], 0.f) * accu[i*4+3] * w;
            *(float4*)(g_hbuf + ((size_t)e*Cn + row)*Fn + n0 + (tx<<2)) = r;
        }
    }
}

__global__ __launch_bounds__(256) void expert_down_kernel(
    const float* __restrict__ wd, float* __restrict__ out)
{
    int e = blockIdx.z;
    int cnt = g_cnt[e];
    int m0 = blockIdx.y * 64;
    if (m0 >= cnt) return;
    int n0 = blockIdx.x * 64;
    __shared__ float As[64*16];
    __shared__ float Bs[16*64];
    __shared__ const float* Arows[64];
    __shared__ int stok[64];
    int tid = threadIdx.x;
    if (tid < 64) {
        int m = m0 + tid;
        stok[tid] = (m < cnt) ? g_tok[e*Cn + m] : 0;
        Arows[tid] = g_hbuf + ((size_t)e*Cn + m) * Fn;  // rows >= cnt are zeros
    }
    __syncthreads();
    float acc[16] = {};
    gemm1_core(Arows, wd + (size_t)e*Fn*Hn, Hn, Fn, n0, acc, As, Bs);
    int tx = tid & 15, ty = tid >> 4;
#pragma unroll
    for (int i = 0; i < 4; i++) {
        int row = m0 + ty*4 + i;
        if (row < cnt) {
            float* op = out + (size_t)stok[ty*4+i]*Hn + n0 + (tx<<2);
            atomicAdd(op + 0, acc[i*4+0]);
            atomicAdd(op + 1, acc[i*4+1]);
            atomicAdd(op + 2, acc[i*4+2]);
            atomicAdd(op + 3, acc[i*4+3]);
        }
    }
}

__global__ void aux_kernel(float* __restrict__ out, int write_aux) {
    __shared__ float red[En];
    int e = threadIdx.x;  // 64 threads
    red[e] = (float)g_totcnt[e] * g_probsum[e];
    __syncthreads();
    for (int s = 32; s > 0; s >>= 1) {
        if (e < s) red[e] += red[e+s];
        __syncthreads();
    }
    if (e == 0 && write_aux) {
        // aux = E * sum_e (totcnt/(T*K)) * (probsum/T)
        out[(size_t)Tn*Hn] = (float)En * red[0] / ((float)Tn * (float)Kn * (float)Tn);
    }
}

// ---------------- launch ----------------
extern "C" void kernel_launch(void* const* d_in, const int* in_sizes, int n_in,
                              void* d_out, int out_size) {
    const float* x   = (const float*)d_in[0];
    const float* rw  = (const float*)d_in[1];
    const float* wg  = (const float*)d_in[2];
    const float* wu  = (const float*)d_in[3];
    const float* wd  = (const float*)d_in[4];
    const float* swg = (const float*)d_in[5];
    const float* swu = (const float*)d_in[6];
    const float* swd = (const float*)d_in[7];
    float* out = (float*)d_out;

    zero_kernel<<<1, 64>>>();
    logits_kernel<<<dim3(En/64, Tn/64), 256>>>(x, rw);
    router_post_kernel<<<Tn, 64>>>();
    hist_kernel<<<NCHUNK, CHSZ>>>();
    scan_kernel<<<1, En>>>();
    pos_kernel<<<NCHUNK, CHSZ>>>();

    shared_gu_kernel<<<dim3(F2n/64, Tn/64, 2), 256>>>(x, swg, swu);
    shared_down_kernel<<<dim3(Hn/64, Tn/64), 256>>>(swd, out);

    expert_gu_kernel<<<dim3(Fn/64, (Cn+63)/64, En), 256>>>(x, wg, wu);
    expert_down_kernel<<<dim3(Hn/64, (Cn+63)/64, En), 256>>>(wd, out);

    int write_aux = (out_size > Tn*Hn) ? 1 : 0;
    aux_kernel<<<1, En>>>(out, write_aux);
}

// round 4
// speedup vs baseline: 1.1623x; 1.1028x over previous
#include <cuda_runtime.h>
#include <math.h>

#define Tn 2048
#define Hn 2048
#define Fn 512
#define En 64
#define Kn 8
#define Cn 320
#define F2n 1024
#define KTn (Kn*Tn)
#define NCHUNK 64
#define CHSZ 256

// ---------------- scratch (device globals; zero-initialized at load) ----------------
__device__ float g_logits[Tn*En];
__device__ int   g_topi[KTn];       // [k*T + t]
__device__ float g_topv[KTn];
__device__ float g_probsum[En];
__device__ int   g_chunkcnt[NCHUNK*En];
__device__ int   g_basecnt[NCHUNK*En];
__device__ int   g_cnt[En];         // capped counts (<= Cn)
__device__ int   g_totcnt[En];      // uncapped (for aux loss)
__device__ int   g_tok[En*Cn];
__device__ float g_wslot[En*Cn];
__device__ float g_hbuf[(size_t)En*Cn*Fn];   // relu(g)*u*w per expert slot
__device__ float g_hs[(size_t)Tn*2*F2n];     // shared-expert hidden

// ---------------- packed f32x2 helpers (Blackwell FFMA2 path) ----------------
typedef unsigned long long ull;

__device__ __forceinline__ ull splat2(float a) {
    ull r; unsigned ai = __float_as_uint(a);
    asm("mov.b64 %0, {%1, %1};" : "=l"(r) : "r"(ai));
    return r;
}
__device__ __forceinline__ void ffma2(ull& d, ull a, ull b) {
    asm("fma.rn.f32x2 %0, %1, %2, %0;" : "+l"(d) : "l"(a), "l"(b));
}
__device__ __forceinline__ float2 unpk(ull v) {
    float2 f;
    asm("mov.b64 {%0, %1}, %2;" : "=f"(f.x), "=f"(f.y) : "l"(v));
    return f;
}

// ---------------- GEMM cores: BM=BN=64, BK=16, 256 threads, 4x4/thread ----------
// FFMA2 inner product, double-buffered smem (1 barrier per k-slab).
// acc layout: acc[i*2+p] = packed columns {n0+tx*4+2p, +2p+1} of row m0+ty*4+i.

__device__ __forceinline__ void gemm1_core(
    const float* const* __restrict__ Arows,
    const float* __restrict__ B, int ldB, int Kd, int n0,
    ull acc[8], float* As, float* Bs)
{
    int tid = threadIdx.x;
    int tx = tid & 15, ty = tid >> 4;
    int lmA = tid >> 2, lkA = (tid & 3) << 2;
    int lkB = tid >> 4, lnB = (tid & 15) << 2;
    const float* Bp = B + (size_t)lkB * ldB + n0 + lnB;

    float4 av = *(const float4*)(Arows[lmA] + lkA);
    float4 bv = *(const float4*)(Bp);
    *(float4*)(As + lmA*16 + lkA) = av;
    *(float4*)(Bs + lkB*64 + lnB) = bv;
    __syncthreads();

    int nslab = Kd >> 4;
#pragma unroll 1
    for (int s = 0; s < nslab; s++) {
        int cur = s & 1, nxt = cur ^ 1;
        if (s + 1 < nslab) {
            av = *(const float4*)(Arows[lmA] + (s+1)*16 + lkA);
            bv = *(const float4*)(Bp + (size_t)(s+1)*16*ldB);
        }
        const float* Asc = As + cur*1024;
        const float* Bsc = Bs + cur*1024;
#pragma unroll
        for (int kk = 0; kk < 16; kk++) {
            ulonglong2 b = *(const ulonglong2*)(Bsc + kk*64 + (tx<<2));
#pragma unroll
            for (int i = 0; i < 4; i++) {
                ull a2 = splat2(Asc[(ty*4+i)*16 + kk]);
                ffma2(acc[i*2+0], a2, b.x);
                ffma2(acc[i*2+1], a2, b.y);
            }
        }
        if (s + 1 < nslab) {
            *(float4*)(As + nxt*1024 + lmA*16 + lkA) = av;
            *(float4*)(Bs + nxt*1024 + lkB*64 + lnB) = bv;
        }
        __syncthreads();
    }
}

__device__ __forceinline__ void gemm2_core(
    const float* const* __restrict__ Arows,
    const float* __restrict__ Bg, const float* __restrict__ Bu,
    int ldB, int Kd, int n0,
    ull accg[8], ull accu[8], float* As, float* Bgs, float* Bus)
{
    int tid = threadIdx.x;
    int tx = tid & 15, ty = tid >> 4;
    int lmA = tid >> 2, lkA = (tid & 3) << 2;
    int lkB = tid >> 4, lnB = (tid & 15) << 2;
    const float* Bgp = Bg + (size_t)lkB * ldB + n0 + lnB;
    const float* Bup = Bu + (size_t)lkB * ldB + n0 + lnB;

    float4 av  = *(const float4*)(Arows[lmA] + lkA);
    float4 bgv = *(const float4*)(Bgp);
    float4 buv = *(const float4*)(Bup);
    *(float4*)(As  + lmA*16 + lkA) = av;
    *(float4*)(Bgs + lkB*64 + lnB) = bgv;
    *(float4*)(Bus + lkB*64 + lnB) = buv;
    __syncthreads();

    int nslab = Kd >> 4;
#pragma unroll 1
    for (int s = 0; s < nslab; s++) {
        int cur = s & 1, nxt = cur ^ 1;
        if (s + 1 < nslab) {
            av  = *(const float4*)(Arows[lmA] + (s+1)*16 + lkA);
            bgv = *(const float4*)(Bgp + (size_t)(s+1)*16*ldB);
            buv = *(const float4*)(Bup + (size_t)(s+1)*16*ldB);
        }
        const float* Asc  = As  + cur*1024;
        const float* Bgsc = Bgs + cur*1024;
        const float* Busc = Bus + cur*1024;
#pragma unroll
        for (int kk = 0; kk < 16; kk++) {
            ulonglong2 bg = *(const ulonglong2*)(Bgsc + kk*64 + (tx<<2));
            ulonglong2 bu = *(const ulonglong2*)(Busc + kk*64 + (tx<<2));
#pragma unroll
            for (int i = 0; i < 4; i++) {
                ull a2 = splat2(Asc[(ty*4+i)*16 + kk]);
                ffma2(accg[i*2+0], a2, bg.x);
                ffma2(accg[i*2+1], a2, bg.y);
                ffma2(accu[i*2+0], a2, bu.x);
                ffma2(accu[i*2+1], a2, bu.y);
            }
        }
        if (s + 1 < nslab) {
            *(float4*)(As  + nxt*1024 + lmA*16 + lkA) = av;
            *(float4*)(Bgs + nxt*1024 + lkB*64 + lnB) = bgv;
            *(float4*)(Bus + nxt*1024 + lkB*64 + lnB) = buv;
        }
        __syncthreads();
    }
}

// ---------------- small kernels ----------------
__global__ void zero_kernel() {
    if (threadIdx.x < En) g_probsum[threadIdx.x] = 0.f;
}

// logits = x @ router_w : M=T, N=E(=64), K=H
__global__ __launch_bounds__(256) void logits_kernel(
    const float* __restrict__ x, const float* __restrict__ rw)
{
    __shared__ __align__(16) float As[2*64*16];
    __shared__ __align__(16) float Bs[2*16*64];
    __shared__ const float* Arows[64];
    int tid = threadIdx.x;
    int m0 = blockIdx.y * 64, n0 = blockIdx.x * 64;
    if (tid < 64) Arows[tid] = x + (size_t)(m0 + tid) * Hn;
    __syncthreads();
    ull acc[8] = {};
    gemm1_core(Arows, rw, En, Hn, n0, acc, As, Bs);
    int tx = tid & 15, ty = tid >> 4;
#pragma unroll
    for (int i = 0; i < 4; i++) {
        float2 p0 = unpk(acc[i*2+0]);
        float2 p1 = unpk(acc[i*2+1]);
        float4 r = make_float4(p0.x, p0.y, p1.x, p1.y);
        *(float4*)(g_logits + (size_t)(m0 + ty*4 + i)*En + n0 + (tx<<2)) = r;
    }
}

// per-token softmax + top-8 + probsum accumulation
__global__ void router_post_kernel() {
    int t = blockIdx.x, tid = threadIdx.x;   // 64 threads
    __shared__ float sp[En];
    __shared__ float red[En];
    float l = g_logits[t*En + tid];
    red[tid] = l; __syncthreads();
    for (int s = 32; s > 0; s >>= 1) {
        if (tid < s) red[tid] = fmaxf(red[tid], red[tid+s]);
        __syncthreads();
    }
    float mx = red[0]; __syncthreads();
    float ex = expf(l - mx);
    red[tid] = ex; __syncthreads();
    for (int s = 32; s > 0; s >>= 1) {
        if (tid < s) red[tid] += red[tid+s];
        __syncthreads();
    }
    float p = ex / red[0];
    sp[tid] = p;
    atomicAdd(&g_probsum[tid], p);
    __syncthreads();
    if (tid == 0) {
        // stable top-8: strict > keeps lowest index on ties (matches lax.top_k)
        for (int k = 0; k < Kn; k++) {
            float bv = -1.f; int bi = 0;
            for (int e = 0; e < En; e++) {
                float v = sp[e];
                if (v > bv) { bv = v; bi = e; }
            }
            g_topi[k*Tn + t] = bi;
            g_topv[k*Tn + t] = bv;
            sp[bi] = -1.f;
        }
    }
}

__global__ void hist_kernel() {
    __shared__ int cnt[En];
    int tid = threadIdx.x;
    if (tid < En) cnt[tid] = 0;
    __syncthreads();
    int a = blockIdx.x * CHSZ + tid;
    int e = g_topi[a];
    atomicAdd(&cnt[e], 1);
    __syncthreads();
    if (tid < En) g_chunkcnt[blockIdx.x*En + tid] = cnt[tid];
}

__global__ void scan_kernel() {
    int e = threadIdx.x;   // 64 threads
    int run = 0;
    for (int c = 0; c < NCHUNK; c++) {
        g_basecnt[c*En + e] = run;
        run += g_chunkcnt[c*En + e];
    }
    g_totcnt[e] = run;
    g_cnt[e] = run < Cn ? run : Cn;
}

__global__ void pos_kernel() {
    __shared__ int se[CHSZ];
    int tid = threadIdx.x;
    int a = blockIdx.x * CHSZ + tid;
    int e = g_topi[a];
    se[tid] = e;
    __syncthreads();
    int rank = 0;
    for (int j = 0; j < tid; j++) rank += (se[j] == e);
    int slot = g_basecnt[blockIdx.x*En + e] + rank;
    if (slot < Cn) {
        int t = a & (Tn - 1);          // a = k*T + t
        g_tok[e*Cn + slot] = t;
        g_wslot[e*Cn + slot] = g_topv[a];
    }
}

// ---------------- shared experts ----------------
__global__ __launch_bounds__(256) void shared_gu_kernel(
    const float* __restrict__ x,
    const float* __restrict__ swg, const float* __restrict__ swu)
{
    __shared__ __align__(16) float As[2*64*16];
    __shared__ __align__(16) float Bgs[2*16*64];
    __shared__ __align__(16) float Bus[2*16*64];
    __shared__ const float* Arows[64];
    int tid = threadIdx.x;
    int e = blockIdx.z;
    int m0 = blockIdx.y * 64, n0 = blockIdx.x * 64;
    if (tid < 64) Arows[tid] = x + (size_t)(m0 + tid) * Hn;
    __syncthreads();
    ull accg[8] = {}, accu[8] = {};
    gemm2_core(Arows, swg + (size_t)e*Hn*F2n, swu + (size_t)e*Hn*F2n,
               F2n, Hn, n0, accg, accu, As, Bgs, Bus);
    int tx = tid & 15, ty = tid >> 4;
#pragma unroll
    for (int i = 0; i < 4; i++) {
        int m = m0 + ty*4 + i;
        float2 g0 = unpk(accg[i*2+0]), g1 = unpk(accg[i*2+1]);
        float2 u0 = unpk(accu[i*2+0]), u1 = unpk(accu[i*2+1]);
        float4 r;
        r.x = fmaxf(g0.x, 0.f) * u0.x;
        r.y = fmaxf(g0.y, 0.f) * u0.y;
        r.z = fmaxf(g1.x, 0.f) * u1.x;
        r.w = fmaxf(g1.y, 0.f) * u1.y;
        *(float4*)(g_hs + (size_t)m*(2*F2n) + (size_t)e*F2n + n0 + (tx<<2)) = r;
    }
}

// out = hs @ swd_flat : M=T, N=H, K=2F2 ; plain store (initializes out)
__global__ __launch_bounds__(256) void shared_down_kernel(
    const float* __restrict__ swd, float* __restrict__ out)
{
    __shared__ __align__(16) float As[2*64*16];
    __shared__ __align__(16) float Bs[2*16*64];
    __shared__ const float* Arows[64];
    int tid = threadIdx.x;
    int m0 = blockIdx.y * 64, n0 = blockIdx.x * 64;
    if (tid < 64) Arows[tid] = g_hs + (size_t)(m0 + tid) * (2*F2n);
    __syncthreads();
    ull acc[8] = {};
    gemm1_core(Arows, swd, Hn, 2*F2n, n0, acc, As, Bs);
    int tx = tid & 15, ty = tid >> 4;
#pragma unroll
    for (int i = 0; i < 4; i++) {
        int m = m0 + ty*4 + i;
        float2 p0 = unpk(acc[i*2+0]);
        float2 p1 = unpk(acc[i*2+1]);
        float4 r = make_float4(p0.x, p0.y, p1.x, p1.y);
        *(float4*)(out + (size_t)m*Hn + n0 + (tx<<2)) = r;
    }
}

// ---------------- expert FFN ----------------
__global__ __launch_bounds__(256) void expert_gu_kernel(
    const float* __restrict__ x,
    const float* __restrict__ wg, const float* __restrict__ wu)
{
    int e = blockIdx.z;
    int cnt = g_cnt[e];
    int m0 = blockIdx.y * 64;
    if (m0 >= cnt) return;
    int n0 = blockIdx.x * 64;
    __shared__ __align__(16) float As[2*64*16];
    __shared__ __align__(16) float Bgs[2*16*64];
    __shared__ __align__(16) float Bus[2*16*64];
    __shared__ const float* Arows[64];
    __shared__ float sw[64];
    int tid = threadIdx.x;
    if (tid < 64) {
        int m = m0 + tid;
        int tk = (m < cnt) ? g_tok[e*Cn + m] : 0;
        Arows[tid] = x + (size_t)tk * Hn;
        sw[tid] = (m < cnt) ? g_wslot[e*Cn + m] : 0.f;
    }
    __syncthreads();
    ull accg[8] = {}, accu[8] = {};
    gemm2_core(Arows, wg + (size_t)e*Hn*Fn, wu + (size_t)e*Hn*Fn,
               Fn, Hn, n0, accg, accu, As, Bgs, Bus);
    int tx = tid & 15, ty = tid >> 4;
#pragma unroll
    for (int i = 0; i < 4; i++) {
        int row = m0 + ty*4 + i;
        if (row < cnt) {
            float w = sw[ty*4 + i];
            float2 g0 = unpk(accg[i*2+0]), g1 = unpk(accg[i*2+1]);
            float2 u0 = unpk(accu[i*2+0]), u1 = unpk(accu[i*2+1]);
            float4 r;
            r.x = fmaxf(g0.x, 0.f) * u0.x * w;
            r.y = fmaxf(g0.y, 0.f) * u0.y * w;
            r.z = fmaxf(g1.x, 0.f) * u1.x * w;
            r.w = fmaxf(g1.y, 0.f) * u1.y * w;
            *(float4*)(g_hbuf + ((size_t)e*Cn + row)*Fn + n0 + (tx<<2)) = r;
        }
    }
}

__global__ __launch_bounds__(256) void expert_down_kernel(
    const float* __restrict__ wd, float* __restrict__ out)
{
    int e = blockIdx.z;
    int cnt = g_cnt[e];
    int m0 = blockIdx.y * 64;
    if (m0 >= cnt) return;
    int n0 = blockIdx.x * 64;
    __shared__ __align__(16) float As[2*64*16];
    __shared__ __align__(16) float Bs[2*16*64];
    __shared__ const float* Arows[64];
    __shared__ int stok[64];
    int tid = threadIdx.x;
    if (tid < 64) {
        int m = m0 + tid;
        stok[tid] = (m < cnt) ? g_tok[e*Cn + m] : 0;
        Arows[tid] = g_hbuf + ((size_t)e*Cn + m) * Fn;  // rows >= cnt are zeros
    }
    __syncthreads();
    ull acc[8] = {};
    gemm1_core(Arows, wd + (size_t)e*Fn*Hn, Hn, Fn, n0, acc, As, Bs);
    int tx = tid & 15, ty = tid >> 4;
#pragma unroll
    for (int i = 0; i < 4; i++) {
        int row = m0 + ty*4 + i;
        if (row < cnt) {
            float2 p0 = unpk(acc[i*2+0]);
            float2 p1 = unpk(acc[i*2+1]);
            float* op = out + (size_t)stok[ty*4+i]*Hn + n0 + (tx<<2);
            atomicAdd(op + 0, p0.x);
            atomicAdd(op + 1, p0.y);
            atomicAdd(op + 2, p1.x);
            atomicAdd(op + 3, p1.y);
        }
    }
}

__global__ void aux_kernel(float* __restrict__ out, int write_aux) {
    __shared__ float red[En];
    int e = threadIdx.x;  // 64 threads
    red[e] = (float)g_totcnt[e] * g_probsum[e];
    __syncthreads();
    for (int s = 32; s > 0; s >>= 1) {
        if (e < s) red[e] += red[e+s];
        __syncthreads();
    }
    if (e == 0 && write_aux) {
        // aux = E * sum_e (totcnt/(T*K)) * (probsum/T)
        out[(size_t)Tn*Hn] = (float)En * red[0] / ((float)Tn * (float)Kn * (float)Tn);
    }
}

// ---------------- launch ----------------
extern "C" void kernel_launch(void* const* d_in, const int* in_sizes, int n_in,
                              void* d_out, int out_size) {
    const float* x   = (const float*)d_in[0];
    const float* rw  = (const float*)d_in[1];
    const float* wg  = (const float*)d_in[2];
    const float* wu  = (const float*)d_in[3];
    const float* wd  = (const float*)d_in[4];
    const float* swg = (const float*)d_in[5];
    const float* swu = (const float*)d_in[6];
    const float* swd = (const float*)d_in[7];
    float* out = (float*)d_out;

    zero_kernel<<<1, 64>>>();
    logits_kernel<<<dim3(En/64, Tn/64), 256>>>(x, rw);
    router_post_kernel<<<Tn, 64>>>();
    hist_kernel<<<NCHUNK, CHSZ>>>();
    scan_kernel<<<1, En>>>();
    pos_kernel<<<NCHUNK, CHSZ>>>();

    shared_gu_kernel<<<dim3(F2n/64, Tn/64, 2), 256>>>(x, swg, swu);
    shared_down_kernel<<<dim3(Hn/64, Tn/64), 256>>>(swd, out);

    expert_gu_kernel<<<dim3(Fn/64, (Cn+63)/64, En), 256>>>(x, wg, wu);
    expert_down_kernel<<<dim3(Hn/64, (Cn+63)/64, En), 256>>>(wd, out);

    int write_aux = (out_size > Tn*Hn) ? 1 : 0;
    aux_kernel<<<1, En>>>(out, write_aux);
}

// round 7
// speedup vs baseline: 1.7150x; 1.4756x over previous
#include <cuda_runtime.h>
#include <math.h>
#include <stdint.h>

#define Tn 2048
#define Hn 2048
#define Fn 512
#define En 64
#define Kn 8
#define Cn 320
#define F2n 1024
#define KTn (Kn*Tn)
#define NCHUNK 64
#define CHSZ 256

typedef unsigned int u32;
typedef unsigned long long u64;

// ---------------- scratch (device globals; zero-initialized at load) ----------------
__device__ float g_logits[Tn*En];
__device__ int   g_topi[KTn];       // [k*T + t]
__device__ float g_topv[KTn];
__device__ float g_probsum[En];
__device__ int   g_chunkcnt[NCHUNK*En];
__device__ int   g_basecnt[NCHUNK*En];
__device__ int   g_cnt[En];
__device__ int   g_totcnt[En];
__device__ int   g_tok[En*Cn];
__device__ float g_wslot[En*Cn];
__device__ float g_hbuf[(size_t)En*Cn*Fn];   // gate raw, then relu(g)*u*w
__device__ float g_hs[(size_t)Tn*2*F2n];     // shared gate raw, then relu(g)*u

// ---------------- packed f32x2 helpers (router logits GEMM stays exact fp32) --------
typedef unsigned long long ull;
__device__ __forceinline__ ull splat2(float a) {
    ull r; unsigned ai = __float_as_uint(a);
    asm("mov.b64 %0, {%1, %1};" : "=l"(r) : "r"(ai));
    return r;
}
__device__ __forceinline__ void ffma2(ull& d, ull a, ull b) {
    asm("fma.rn.f32x2 %0, %1, %2, %0;" : "+l"(d) : "l"(a), "l"(b));
}
__device__ __forceinline__ float2 unpk(ull v) {
    float2 f;
    asm("mov.b64 {%0, %1}, %2;" : "=f"(f.x), "=f"(f.y) : "l"(v));
    return f;
}

__device__ __forceinline__ void gemm1_core(
    const float* const* __restrict__ Arows,
    const float* __restrict__ B, int ldB, int Kd, int n0,
    ull acc[8], float* As, float* Bs)
{
    int tid = threadIdx.x;
    int tx = tid & 15, ty = tid >> 4;
    int lmA = tid >> 2, lkA = (tid & 3) << 2;
    int lkB = tid >> 4, lnB = (tid & 15) << 2;
    const float* Bp = B + (size_t)lkB * ldB + n0 + lnB;
    float4 av = *(const float4*)(Arows[lmA] + lkA);
    float4 bv = *(const float4*)(Bp);
    *(float4*)(As + lmA*16 + lkA) = av;
    *(float4*)(Bs + lkB*64 + lnB) = bv;
    __syncthreads();
    int nslab = Kd >> 4;
#pragma unroll 1
    for (int s = 0; s < nslab; s++) {
        int cur = s & 1, nxt = cur ^ 1;
        if (s + 1 < nslab) {
            av = *(const float4*)(Arows[lmA] + (s+1)*16 + lkA);
            bv = *(const float4*)(Bp + (size_t)(s+1)*16*ldB);
        }
        const float* Asc = As + cur*1024;
        const float* Bsc = Bs + cur*1024;
#pragma unroll
        for (int kk = 0; kk < 16; kk++) {
            ulonglong2 b = *(const ulonglong2*)(Bsc + kk*64 + (tx<<2));
#pragma unroll
            for (int i = 0; i < 4; i++) {
                ull a2 = splat2(Asc[(ty*4+i)*16 + kk]);
                ffma2(acc[i*2+0], a2, b.x);
                ffma2(acc[i*2+1], a2, b.y);
            }
        }
        if (s + 1 < nslab) {
            *(float4*)(As + nxt*1024 + lmA*16 + lkA) = av;
            *(float4*)(Bs + nxt*1024 + lkB*64 + lnB) = bv;
        }
        __syncthreads();
    }
}

// ---------------- router pipeline ----------------
__global__ void zero_kernel() {
    if (threadIdx.x < En) g_probsum[threadIdx.x] = 0.f;
}

__global__ __launch_bounds__(256) void logits_kernel(
    const float* __restrict__ x, const float* __restrict__ rw)
{
    __shared__ __align__(16) float As[2*64*16];
    __shared__ __align__(16) float Bs[2*16*64];
    __shared__ const float* Arows[64];
    int tid = threadIdx.x;
    int m0 = blockIdx.y * 64, n0 = blockIdx.x * 64;
    if (tid < 64) Arows[tid] = x + (size_t)(m0 + tid) * Hn;
    __syncthreads();
    ull acc[8] = {};
    gemm1_core(Arows, rw, En, Hn, n0, acc, As, Bs);
    int tx = tid & 15, ty = tid >> 4;
#pragma unroll
    for (int i = 0; i < 4; i++) {
        float2 p0 = unpk(acc[i*2+0]);
        float2 p1 = unpk(acc[i*2+1]);
        float4 r = make_float4(p0.x, p0.y, p1.x, p1.y);
        *(float4*)(g_logits + (size_t)(m0 + ty*4 + i)*En + n0 + (tx<<2)) = r;
    }
}

__global__ void router_post_kernel() {
    int t = blockIdx.x, tid = threadIdx.x;   // 64 threads
    __shared__ float sp[En];
    __shared__ float red[En];
    float l = g_logits[t*En + tid];
    red[tid] = l; __syncthreads();
    for (int s = 32; s > 0; s >>= 1) {
        if (tid < s) red[tid] = fmaxf(red[tid], red[tid+s]);
        __syncthreads();
    }
    float mx = red[0]; __syncthreads();
    float ex = expf(l - mx);
    red[tid] = ex; __syncthreads();
    for (int s = 32; s > 0; s >>= 1) {
        if (tid < s) red[tid] += red[tid+s];
        __syncthreads();
    }
    float p = ex / red[0];
    sp[tid] = p;
    atomicAdd(&g_probsum[tid], p);
    __syncthreads();
    if (tid == 0) {
        for (int k = 0; k < Kn; k++) {   // strict > keeps lowest index on ties
            float bv = -1.f; int bi = 0;
            for (int e = 0; e < En; e++) {
                float v = sp[e];
                if (v > bv) { bv = v; bi = e; }
            }
            g_topi[k*Tn + t] = bi;
            g_topv[k*Tn + t] = bv;
            sp[bi] = -1.f;
        }
    }
}

__global__ void hist_kernel() {
    __shared__ int cnt[En];
    int tid = threadIdx.x;
    if (tid < En) cnt[tid] = 0;
    __syncthreads();
    int a = blockIdx.x * CHSZ + tid;
    atomicAdd(&cnt[g_topi[a]], 1);
    __syncthreads();
    if (tid < En) g_chunkcnt[blockIdx.x*En + tid] = cnt[tid];
}

__global__ void scan_kernel() {
    int e = threadIdx.x;   // 64 threads
    int run = 0;
    for (int c = 0; c < NCHUNK; c++) {
        g_basecnt[c*En + e] = run;
        run += g_chunkcnt[c*En + e];
    }
    g_totcnt[e] = run;
    g_cnt[e] = run < Cn ? run : Cn;
}

__global__ void pos_kernel() {
    __shared__ int se[CHSZ];
    int tid = threadIdx.x;
    int a = blockIdx.x * CHSZ + tid;
    int e = g_topi[a];
    se[tid] = e;
    __syncthreads();
    int rank = 0;
    for (int j = 0; j < tid; j++) rank += (se[j] == e);
    int slot = g_basecnt[blockIdx.x*En + e] + rank;
    if (slot < Cn) {
        int t = a & (Tn - 1);          // a = k*T + t
        g_tok[e*Cn + slot] = t;
        g_wslot[e*Cn + slot] = g_topv[a];
    }
}

__global__ void aux_kernel(float* __restrict__ out, int write_aux) {
    __shared__ float red[En];
    int e = threadIdx.x;
    red[e] = (float)g_totcnt[e] * g_probsum[e];
    __syncthreads();
    for (int s = 32; s > 0; s >>= 1) {
        if (e < s) red[e] += red[e+s];
        __syncthreads();
    }
    if (e == 0 && write_aux)
        out[(size_t)Tn*Hn] = (float)En * red[0] / ((float)Tn * (float)Kn * (float)Tn);
}

// ================= tf32 mma.sync GEMM family (legacy tensor-core path) =================
__device__ __forceinline__ u32 tf32h(float x){
    u32 r; asm("cvt.rna.tf32.f32 %0, %1;":"=r"(r):"f"(x));
    return r;
}
__device__ __forceinline__ void mma8(float* c, u32 a0, u32 a1, u32 a2, u32 a3,
                                     u32 b0, u32 b1){
    asm volatile("mma.sync.aligned.m16n8k8.row.col.f32.tf32.tf32.f32 "
        "{%0,%1,%2,%3}, {%4,%5,%6,%7}, {%8,%9}, {%0,%1,%2,%3};"
        : "+f"(c[0]),"+f"(c[1]),"+f"(c[2]),"+f"(c[3])
        : "r"(a0),"r"(a1),"r"(a2),"r"(a3),"r"(b0),"r"(b1));
}

// smem layout per buffer (u32 units): Ah[128*36]=4608, Al[4608], Bs[4608] -> 13824
#define PL 4608
#define BUFU 13824
#define SMB (2*BUFU*4)

// MODE 0: shared gate  A=x           B=swg[e], ldB=F2n -> g_hs raw
// MODE 1: shared up    A=x           B=swu[e]          -> g_hs = relu(g)*u
// MODE 2: expert gate  A=x gathered  B=wg[e],  ldB=Fn  -> g_hbuf raw   (rows<cnt)
// MODE 3: expert up    A=x gathered  B=wu[e]           -> g_hbuf=relu(g)*u*w
// MODE 4: shared down  A=g_hs        B=swd,    ldB=Hn  -> out plain store
// MODE 5: expert down  A=g_hbuf      B=wd[e],  ldB=Hn  -> atomicAdd out
template<int MODE>
__global__ __launch_bounds__(256, 1) void mm_s(
    const float* __restrict__ X, const float* __restrict__ B,
    float* __restrict__ out)
{
    extern __shared__ u32 sm[];
    int tid = threadIdx.x, lane = tid & 31, wid = tid >> 5;
    int warp_m = wid & 3, warp_n = wid >> 2;     // 4 x 2 warps
    int e = blockIdx.z;
    int m0 = blockIdx.y * 128, n0 = blockIdx.x * 128;

    int cnt = Tn, Kd = Hn, ldB = F2n;
    const float* Bp0 = B;
    if (MODE == 0 || MODE == 1) { Bp0 = B + (size_t)e*Hn*F2n; }
    if (MODE == 2 || MODE == 3) {
        cnt = g_cnt[e]; if (m0 >= cnt) return;
        ldB = Fn; Bp0 = B + (size_t)e*Hn*Fn;
    }
    if (MODE == 4) { Kd = 2*F2n; ldB = Hn; }
    if (MODE == 5) {
        cnt = g_cnt[e]; if (m0 >= cnt) return;
        Kd = Fn; ldB = Hn; Bp0 = B + (size_t)e*Fn*Hn;
    }

    // A staging: 2 threads per row, 16 floats each
    int arow = tid >> 1, ahalf = (tid & 1) * 16;
    const float* rp;
    if (MODE <= 1) rp = X + (size_t)(m0 + arow) * Hn;
    else if (MODE <= 3) {
        int m = m0 + arow;
        int tk = (m < cnt) ? g_tok[e*Cn + m] : 0;
        rp = X + (size_t)tk * Hn;
    } else if (MODE == 4) rp = g_hs + (size_t)(m0 + arow) * (2*F2n);
    else {
        int m = m0 + arow; if (m > Cn-1) m = Cn-1;   // rows>=cnt guarded at store
        rp = g_hbuf + ((size_t)e*Cn + m) * Fn;
    }

    // B staging: thread = one n column (128), 16 k's
    int bn = tid & 127, bkq = tid >> 7;
    const float* bp = Bp0 + (size_t)bkq * 16 * ldB + n0 + bn;

    float acc[2][8][4];
#pragma unroll
    for (int i = 0; i < 2; i++)
#pragma unroll
    for (int j = 0; j < 8; j++)
#pragma unroll
    for (int q = 0; q < 4; q++) acc[i][j][q] = 0.f;

    float va[16], vb[16];

#define LDA(s) do{ const float4* _a = (const float4*)(rp + (s)*32 + ahalf); \
    *(float4*)(va+0)=_a[0]; *(float4*)(va+4)=_a[1]; \
    *(float4*)(va+8)=_a[2]; *(float4*)(va+12)=_a[3]; }while(0)
#define LDBV(s) do{ const float* _b = bp + (size_t)(s)*32*ldB; \
    _Pragma("unroll") for (int j = 0; j < 16; j++) vb[j] = _b[(size_t)j*ldB]; }while(0)
#define STO(bsel) do{ \
    u32* Ah = sm + (bsel)*BUFU; u32* Al = Ah + PL; u32* Bsm = Ah + 2*PL; \
    u32 abase = arow*36 + ahalf; \
    _Pragma("unroll") for (int q = 0; q < 4; q++){ \
        u32 h[4], l[4]; \
        _Pragma("unroll") for (int j = 0; j < 4; j++){ \
            float f = va[q*4+j]; \
            h[j] = tf32h(f); \
            l[j] = tf32h(f - __uint_as_float(h[j])); } \
        *(uint4*)(Ah + abase + q*4) = make_uint4(h[0],h[1],h[2],h[3]); \
        *(uint4*)(Al + abase + q*4) = make_uint4(l[0],l[1],l[2],l[3]); } \
    u32 bbase = bn*36 + bkq*16; \
    _Pragma("unroll") for (int q = 0; q < 4; q++){ \
        u32 r[4]; \
        _Pragma("unroll") for (int j = 0; j < 4; j++) r[j] = tf32h(vb[q*4+j]); \
        *(uint4*)(Bsm + bbase + q*4) = make_uint4(r[0],r[1],r[2],r[3]); } }while(0)

    LDA(0); LDBV(0); STO(0);
    __syncthreads();

    int nslab = Kd / 32;
    int grp = lane >> 2, tig = lane & 3;
#pragma unroll 1
    for (int s = 0; s < nslab; s++) {
        if (s + 1 < nslab) { LDA(s+1); LDBV(s+1); }
        const u32* Ah = sm + (s & 1)*BUFU;
        const u32* Al = Ah + PL;
        const u32* Bsm = Ah + 2*PL;
#pragma unroll
        for (int kk = 0; kk < 4; kk++) {
            int kb = kk * 8;
            u32 ah[2][4], al[2][4], bf[8][2];
#pragma unroll
            for (int mt = 0; mt < 2; mt++) {
                u32 b0 = (u32)(warp_m*32 + mt*16 + grp)*36 + kb + tig;
                ah[mt][0] = Ah[b0];       ah[mt][1] = Ah[b0 + 288];
                ah[mt][2] = Ah[b0 + 4];   ah[mt][3] = Ah[b0 + 292];
                al[mt][0] = Al[b0];       al[mt][1] = Al[b0 + 288];
                al[mt][2] = Al[b0 + 4];   al[mt][3] = Al[b0 + 292];
            }
#pragma unroll
            for (int nt = 0; nt < 8; nt++) {
                u32 bb = (u32)(warp_n*64 + nt*8 + grp)*36 + kb + tig;
                bf[nt][0] = Bsm[bb];
                bf[nt][1] = Bsm[bb + 4];
            }
#pragma unroll
            for (int mt = 0; mt < 2; mt++)
#pragma unroll
            for (int nt = 0; nt < 8; nt++) {
                mma8(acc[mt][nt], ah[mt][0], ah[mt][1], ah[mt][2], ah[mt][3],
                     bf[nt][0], bf[nt][1]);
                mma8(acc[mt][nt], al[mt][0], al[mt][1], al[mt][2], al[mt][3],
                     bf[nt][0], bf[nt][1]);
            }
        }
        if (s + 1 < nslab) STO((s+1) & 1);
        __syncthreads();
    }

    // epilogue
#pragma unroll
    for (int mt = 0; mt < 2; mt++) {
#pragma unroll
        for (int half = 0; half < 2; half++) {
            int row = warp_m*32 + mt*16 + grp + half*8;
            int gr = m0 + row;
            bool ok = true;
            float w = 1.f; int tok = 0;
            if (MODE == 2 || MODE == 3 || MODE == 5) ok = (gr < cnt);
            if (MODE == 3 && ok) w = g_wslot[e*Cn + gr];
            if (MODE == 5 && ok) tok = g_tok[e*Cn + gr];
#pragma unroll
            for (int nt = 0; nt < 8; nt++) {
                float c0 = acc[mt][nt][half*2+0];
                float c1 = acc[mt][nt][half*2+1];
                int col = n0 + warp_n*64 + nt*8 + tig*2;
                if (MODE == 0) {
                    float2* p = (float2*)(g_hs + (size_t)gr*(2*F2n) + (size_t)e*F2n + col);
                    *p = make_float2(c0, c1);
                } else if (MODE == 1) {
                    float2* p = (float2*)(g_hs + (size_t)gr*(2*F2n) + (size_t)e*F2n + col);
                    float2 g = *p;
                    *p = make_float2(fmaxf(g.x, 0.f)*c0, fmaxf(g.y, 0.f)*c1);
                } else if (MODE == 2) {
                    if (ok) {
                        float2* p = (float2*)(g_hbuf + ((size_t)e*Cn + gr)*Fn + col);
                        *p = make_float2(c0, c1);
                    }
                } else if (MODE == 3) {
                    if (ok) {
                        float2* p = (float2*)(g_hbuf + ((size_t)e*Cn + gr)*Fn + col);
                        float2 g = *p;
                        *p = make_float2(fmaxf(g.x, 0.f)*c0*w, fmaxf(g.y, 0.f)*c1*w);
                    }
                } else if (MODE == 4) {
                    float2* p = (float2*)(out + (size_t)gr*Hn + col);
                    *p = make_float2(c0, c1);
                } else {
                    if (ok) {
                        float* p = out + (size_t)tok*Hn + col;
                        atomicAdd(p + 0, c0);
                        atomicAdd(p + 1, c1);
                    }
                }
            }
        }
    }
#undef LDA
#undef LDBV
#undef STO
}

// ---------------- launch ----------------
extern "C" void kernel_launch(void* const* d_in, const int* in_sizes, int n_in,
                              void* d_out, int out_size) {
    const float* x   = (const float*)d_in[0];
    const float* rw  = (const float*)d_in[1];
    const float* wg  = (const float*)d_in[2];
    const float* wu  = (const float*)d_in[3];
    const float* wd  = (const float*)d_in[4];
    const float* swg = (const float*)d_in[5];
    const float* swu = (const float*)d_in[6];
    const float* swd = (const float*)d_in[7];
    float* out = (float*)d_out;

    cudaFuncSetAttribute(mm_s<0>, cudaFuncAttributeMaxDynamicSharedMemorySize, SMB);
    cudaFuncSetAttribute(mm_s<1>, cudaFuncAttributeMaxDynamicSharedMemorySize, SMB);
    cudaFuncSetAttribute(mm_s<2>, cudaFuncAttributeMaxDynamicSharedMemorySize, SMB);
    cudaFuncSetAttribute(mm_s<3>, cudaFuncAttributeMaxDynamicSharedMemorySize, SMB);
    cudaFuncSetAttribute(mm_s<4>, cudaFuncAttributeMaxDynamicSharedMemorySize, SMB);
    cudaFuncSetAttribute(mm_s<5>, cudaFuncAttributeMaxDynamicSharedMemorySize, SMB);

    zero_kernel<<<1, 64>>>();
    logits_kernel<<<dim3(En/64, Tn/64), 256>>>(x, rw);
    router_post_kernel<<<Tn, 64>>>();
    hist_kernel<<<NCHUNK, CHSZ>>>();
    scan_kernel<<<1, En>>>();
    pos_kernel<<<NCHUNK, CHSZ>>>();

    // shared gate -> shared up (fuses relu(g)*u into g_hs)
    mm_s<0><<<dim3(F2n/128, Tn/128, 2), 256, SMB>>>(x, swg, out);
    mm_s<1><<<dim3(F2n/128, Tn/128, 2), 256, SMB>>>(x, swu, out);
    // expert gate -> expert up (fuses relu(g)*u*w into g_hbuf)
    mm_s<2><<<dim3(Fn/128, (Cn+127)/128, En), 256, SMB>>>(x, wg, out);
    mm_s<3><<<dim3(Fn/128, (Cn+127)/128, En), 256, SMB>>>(x, wu, out);
    // shared down initializes out; expert down accumulates
    mm_s<4><<<dim3(Hn/128, Tn/128, 1), 256, SMB>>>(x, swd, out);
    mm_s<5><<<dim3(Hn/128, (Cn+127)/128, En), 256, SMB>>>(x, wd, out);

    int write_aux = (out_size > Tn*Hn) ? 1 : 0;
    aux_kernel<<<1, En>>>(out, write_aux);
}

// round 8
// speedup vs baseline: 2.2751x; 1.3266x over previous
#include <cuda_runtime.h>
#include <math.h>
#include <stdint.h>

#define Tn 2048
#define Hn 2048
#define Fn 512
#define En 64
#define Kn 8
#define Cn 320
#define F2n 1024
#define KTn (Kn*Tn)
#define NCHUNK 64
#define CHSZ 256

typedef unsigned int u32;
typedef unsigned long long u64;

// ---------------- scratch (device globals; zero-initialized at load) ----------------
__device__ float g_logits[Tn*En];
__device__ int   g_topi[KTn];       // [k*T + t]
__device__ float g_topv[KTn];
__device__ float g_probsum[En];
__device__ int   g_chunkcnt[NCHUNK*En];
__device__ int   g_basecnt[NCHUNK*En];
__device__ int   g_cnt[En];
__device__ int   g_totcnt[En];
__device__ int   g_tok[En*Cn];
__device__ float g_wslot[En*Cn];
__device__ float g_hbuf[(size_t)En*Cn*Fn];   // gate raw, then relu(g)*u*w
__device__ float g_hs[(size_t)Tn*2*F2n];     // shared gate raw, then relu(g)*u

// ---------------- packed f32x2 helpers (router logits GEMM stays exact fp32) --------
typedef unsigned long long ull;
__device__ __forceinline__ ull splat2(float a) {
    ull r; unsigned ai = __float_as_uint(a);
    asm("mov.b64 %0, {%1, %1};" : "=l"(r) : "r"(ai));
    return r;
}
__device__ __forceinline__ void ffma2(ull& d, ull a, ull b) {
    asm("fma.rn.f32x2 %0, %1, %2, %0;" : "+l"(d) : "l"(a), "l"(b));
}
__device__ __forceinline__ float2 unpk(ull v) {
    float2 f;
    asm("mov.b64 {%0, %1}, %2;" : "=f"(f.x), "=f"(f.y) : "l"(v));
    return f;
}

__device__ __forceinline__ void gemm1_core(
    const float* const* __restrict__ Arows,
    const float* __restrict__ B, int ldB, int Kd, int n0,
    ull acc[8], float* As, float* Bs)
{
    int tid = threadIdx.x;
    int tx = tid & 15, ty = tid >> 4;
    int lmA = tid >> 2, lkA = (tid & 3) << 2;
    int lkB = tid >> 4, lnB = (tid & 15) << 2;
    const float* Bp = B + (size_t)lkB * ldB + n0 + lnB;
    float4 av = *(const float4*)(Arows[lmA] + lkA);
    float4 bv = *(const float4*)(Bp);
    *(float4*)(As + lmA*16 + lkA) = av;
    *(float4*)(Bs + lkB*64 + lnB) = bv;
    __syncthreads();
    int nslab = Kd >> 4;
#pragma unroll 1
    for (int s = 0; s < nslab; s++) {
        int cur = s & 1, nxt = cur ^ 1;
        if (s + 1 < nslab) {
            av = *(const float4*)(Arows[lmA] + (s+1)*16 + lkA);
            bv = *(const float4*)(Bp + (size_t)(s+1)*16*ldB);
        }
        const float* Asc = As + cur*1024;
        const float* Bsc = Bs + cur*1024;
#pragma unroll
        for (int kk = 0; kk < 16; kk++) {
            ulonglong2 b = *(const ulonglong2*)(Bsc + kk*64 + (tx<<2));
#pragma unroll
            for (int i = 0; i < 4; i++) {
                ull a2 = splat2(Asc[(ty*4+i)*16 + kk]);
                ffma2(acc[i*2+0], a2, b.x);
                ffma2(acc[i*2+1], a2, b.y);
            }
        }
        if (s + 1 < nslab) {
            *(float4*)(As + nxt*1024 + lmA*16 + lkA) = av;
            *(float4*)(Bs + nxt*1024 + lkB*64 + lnB) = bv;
        }
        __syncthreads();
    }
}

// ---------------- router pipeline ----------------
__global__ void zero_kernel() {
    if (threadIdx.x < En) g_probsum[threadIdx.x] = 0.f;
}

__global__ __launch_bounds__(256) void logits_kernel(
    const float* __restrict__ x, const float* __restrict__ rw)
{
    __shared__ __align__(16) float As[2*64*16];
    __shared__ __align__(16) float Bs[2*16*64];
    __shared__ const float* Arows[64];
    int tid = threadIdx.x;
    int m0 = blockIdx.y * 64, n0 = blockIdx.x * 64;
    if (tid < 64) Arows[tid] = x + (size_t)(m0 + tid) * Hn;
    __syncthreads();
    ull acc[8] = {};
    gemm1_core(Arows, rw, En, Hn, n0, acc, As, Bs);
    int tx = tid & 15, ty = tid >> 4;
#pragma unroll
    for (int i = 0; i < 4; i++) {
        float2 p0 = unpk(acc[i*2+0]);
        float2 p1 = unpk(acc[i*2+1]);
        float4 r = make_float4(p0.x, p0.y, p1.x, p1.y);
        *(float4*)(g_logits + (size_t)(m0 + ty*4 + i)*En + n0 + (tx<<2)) = r;
    }
}

__global__ void router_post_kernel() {
    int t = blockIdx.x, tid = threadIdx.x;   // 64 threads
    __shared__ float sp[En];
    __shared__ float red[En];
    float l = g_logits[t*En + tid];
    red[tid] = l; __syncthreads();
    for (int s = 32; s > 0; s >>= 1) {
        if (tid < s) red[tid] = fmaxf(red[tid], red[tid+s]);
        __syncthreads();
    }
    float mx = red[0]; __syncthreads();
    float ex = expf(l - mx);
    red[tid] = ex; __syncthreads();
    for (int s = 32; s > 0; s >>= 1) {
        if (tid < s) red[tid] += red[tid+s];
        __syncthreads();
    }
    float p = ex / red[0];
    sp[tid] = p;
    atomicAdd(&g_probsum[tid], p);
    __syncthreads();
    if (tid == 0) {
        for (int k = 0; k < Kn; k++) {   // strict > keeps lowest index on ties
            float bv = -1.f; int bi = 0;
            for (int e = 0; e < En; e++) {
                float v = sp[e];
                if (v > bv) { bv = v; bi = e; }
            }
            g_topi[k*Tn + t] = bi;
            g_topv[k*Tn + t] = bv;
            sp[bi] = -1.f;
        }
    }
}

__global__ void hist_kernel() {
    __shared__ int cnt[En];
    int tid = threadIdx.x;
    if (tid < En) cnt[tid] = 0;
    __syncthreads();
    int a = blockIdx.x * CHSZ + tid;
    atomicAdd(&cnt[g_topi[a]], 1);
    __syncthreads();
    if (tid < En) g_chunkcnt[blockIdx.x*En + tid] = cnt[tid];
}

__global__ void scan_kernel() {
    int e = threadIdx.x;   // 64 threads
    int run = 0;
    for (int c = 0; c < NCHUNK; c++) {
        g_basecnt[c*En + e] = run;
        run += g_chunkcnt[c*En + e];
    }
    g_totcnt[e] = run;
    g_cnt[e] = run < Cn ? run : Cn;
}

__global__ void pos_kernel() {
    __shared__ int se[CHSZ];
    int tid = threadIdx.x;
    int a = blockIdx.x * CHSZ + tid;
    int e = g_topi[a];
    se[tid] = e;
    __syncthreads();
    int rank = 0;
    for (int j = 0; j < tid; j++) rank += (se[j] == e);
    int slot = g_basecnt[blockIdx.x*En + e] + rank;
    if (slot < Cn) {
        int t = a & (Tn - 1);          // a = k*T + t
        g_tok[e*Cn + slot] = t;
        g_wslot[e*Cn + slot] = g_topv[a];
    }
}

__global__ void aux_kernel(float* __restrict__ out, int write_aux) {
    __shared__ float red[En];
    int e = threadIdx.x;
    red[e] = (float)g_totcnt[e] * g_probsum[e];
    __syncthreads();
    for (int s = 32; s > 0; s >>= 1) {
        if (e < s) red[e] += red[e+s];
        __syncthreads();
    }
    if (e == 0 && write_aux)
        out[(size_t)Tn*Hn] = (float)En * red[0] / ((float)Tn * (float)Kn * (float)Tn);
}

// ================= tf32 mma.sync GEMM family (single-pass, LDS.64 fragments) ========
__device__ __forceinline__ u32 tf32h(float x){
    u32 r; asm("cvt.rna.tf32.f32 %0, %1;":"=r"(r):"f"(x));
    return r;
}
__device__ __forceinline__ void mma8(float* c, u32 a0, u32 a1, u32 a2, u32 a3,
                                     u32 b0, u32 b1){
    asm volatile("mma.sync.aligned.m16n8k8.row.col.f32.tf32.tf32.f32 "
        "{%0,%1,%2,%3}, {%4,%5,%6,%7}, {%8,%9}, {%0,%1,%2,%3};"
        : "+f"(c[0]),"+f"(c[1]),"+f"(c[2]),"+f"(c[3])
        : "r"(a0),"r"(a1),"r"(a2),"r"(a3),"r"(b0),"r"(b1));
}

// Packed-pair smem layout: element (row, k) at row*40 + (k>>3)*8 + (k&3)*2 + ((k>>2)&1).
// k and k+4 are adjacent -> every MMA fragment pair loads as one LDS.64.
// Row stride 40 u32 (== 8 mod 32): 64-bit loads conflict-free per half-warp phase.
#define SROW 40
#define APL  (128*SROW)          // 5120 u32 per plane
#define BUFU (2*APL)             // A + B planes
#define SMB  (2*BUFU*4)          // double-buffered, bytes (81920)

// MODE 0: shared gate  A=x           B=swg[e], ldB=F2n -> g_hs raw
// MODE 1: shared up    A=x           B=swu[e]          -> g_hs = relu(g)*u
// MODE 2: expert gate  A=x gathered  B=wg[e],  ldB=Fn  -> g_hbuf raw   (rows<cnt)
// MODE 3: expert up    A=x gathered  B=wu[e]           -> g_hbuf=relu(g)*u*w
// MODE 4: shared down  A=g_hs        B=swd,    ldB=Hn  -> out plain store
// MODE 5: expert down  A=g_hbuf      B=wd[e],  ldB=Hn  -> atomicAdd out
template<int MODE>
__global__ __launch_bounds__(256, 1) void mm_s(
    const float* __restrict__ X, const float* __restrict__ B,
    float* __restrict__ out)
{
    extern __shared__ u32 sm[];
    int tid = threadIdx.x, lane = tid & 31, wid = tid >> 5;
    int warp_m = wid & 3, warp_n = wid >> 2;     // 4 x 2 warps
    int e = blockIdx.z;
    int m0 = blockIdx.y * 128, n0 = blockIdx.x * 128;

    int cnt = Tn, Kd = Hn, ldB = F2n;
    const float* Bp0 = B;
    if (MODE == 0 || MODE == 1) { Bp0 = B + (size_t)e*Hn*F2n; }
    if (MODE == 2 || MODE == 3) {
        cnt = g_cnt[e]; if (m0 >= cnt) return;
        ldB = Fn; Bp0 = B + (size_t)e*Hn*Fn;
    }
    if (MODE == 4) { Kd = 2*F2n; ldB = Hn; }
    if (MODE == 5) {
        cnt = g_cnt[e]; if (m0 >= cnt) return;
        Kd = Fn; ldB = Hn; Bp0 = B + (size_t)e*Fn*Hn;
    }

    // A staging: 2 threads per row, 16 floats each
    int arow = tid >> 1, ahalf = (tid & 1) * 16;
    const float* rp;
    if (MODE <= 1) rp = X + (size_t)(m0 + arow) * Hn;
    else if (MODE <= 3) {
        int m = m0 + arow;
        int tk = (m < cnt) ? g_tok[e*Cn + m] : 0;
        rp = X + (size_t)tk * Hn;
    } else if (MODE == 4) rp = g_hs + (size_t)(m0 + arow) * (2*F2n);
    else {
        int m = m0 + arow; if (m > Cn-1) m = Cn-1;   // rows>=cnt guarded at store
        rp = g_hbuf + ((size_t)e*Cn + m) * Fn;
    }

    // B staging: thread = one n column (128), 16 k's
    int bn = tid & 127, bkq = tid >> 7;
    const float* bp = Bp0 + (size_t)bkq * 16 * ldB + n0 + bn;

    float acc[2][8][4];
#pragma unroll
    for (int i = 0; i < 2; i++)
#pragma unroll
    for (int j = 0; j < 8; j++)
#pragma unroll
    for (int q = 0; q < 4; q++) acc[i][j][q] = 0.f;

    float va[16], vb[16];

#define LDA(s) do{ const float4* _a = (const float4*)(rp + (s)*32 + ahalf); \
    *(float4*)(va+0)=_a[0]; *(float4*)(va+4)=_a[1]; \
    *(float4*)(va+8)=_a[2]; *(float4*)(va+12)=_a[3]; }while(0)
#define LDBV(s) do{ const float* _b = bp + (size_t)(s)*32*ldB; \
    _Pragma("unroll") for (int j = 0; j < 16; j++) vb[j] = _b[(size_t)j*ldB]; }while(0)
// paired store: k and k+4 adjacent (one STS.64)
#define STO(bsel) do{ \
    u32* Ah = sm + (bsel)*BUFU; u32* Bsm = Ah + APL; \
    u32 abase = (u32)arow*SROW + ahalf; \
    _Pragma("unroll") for (int q = 0; q < 2; q++){ \
        _Pragma("unroll") for (int j = 0; j < 4; j++){ \
            int jj = q*8 + j; \
            u32 h0 = tf32h(va[jj]), h1 = tf32h(va[jj+4]); \
            *(uint2*)(Ah + abase + q*8 + j*2) = make_uint2(h0, h1); } } \
    u32 bbase = (u32)bn*SROW + bkq*16; \
    _Pragma("unroll") for (int q = 0; q < 2; q++){ \
        _Pragma("unroll") for (int j = 0; j < 4; j++){ \
            int jj = q*8 + j; \
            u32 h0 = tf32h(vb[jj]), h1 = tf32h(vb[jj+4]); \
            *(uint2*)(Bsm + bbase + q*8 + j*2) = make_uint2(h0, h1); } } \
}while(0)

    LDA(0); LDBV(0); STO(0);
    __syncthreads();

    int nslab = Kd / 32;
    int grp = lane >> 2, tig = lane & 3;
#pragma unroll 1
    for (int s = 0; s < nslab; s++) {
        if (s + 1 < nslab) { LDA(s+1); LDBV(s+1); }
        const u32* Ah = sm + (s & 1)*BUFU;
        const u32* Bsm = Ah + APL;
#pragma unroll
        for (int kk = 0; kk < 4; kk++) {
            int kb = kk * 8;
            uint2 a02[2], a13[2], bf[8];
#pragma unroll
            for (int mt = 0; mt < 2; mt++) {
                u32 r0 = (u32)(warp_m*32 + mt*16 + grp)*SROW + kb + tig*2;
                a02[mt] = *(const uint2*)(Ah + r0);
                a13[mt] = *(const uint2*)(Ah + r0 + 8*SROW);
            }
#pragma unroll
            for (int nt = 0; nt < 8; nt++) {
                u32 bb = (u32)(warp_n*64 + nt*8 + grp)*SROW + kb + tig*2;
                bf[nt] = *(const uint2*)(Bsm + bb);
            }
#pragma unroll
            for (int mt = 0; mt < 2; mt++)
#pragma unroll
            for (int nt = 0; nt < 8; nt++) {
                mma8(acc[mt][nt], a02[mt].x, a13[mt].x, a02[mt].y, a13[mt].y,
                     bf[nt].x, bf[nt].y);
            }
        }
        if (s + 1 < nslab) STO((s+1) & 1);
        __syncthreads();
    }

    // epilogue
#pragma unroll
    for (int mt = 0; mt < 2; mt++) {
#pragma unroll
        for (int half = 0; half < 2; half++) {
            int row = warp_m*32 + mt*16 + grp + half*8;
            int gr = m0 + row;
            bool ok = true;
            float w = 1.f; int tok = 0;
            if (MODE == 2 || MODE == 3 || MODE == 5) ok = (gr < cnt);
            if (MODE == 3 && ok) w = g_wslot[e*Cn + gr];
            if (MODE == 5 && ok) tok = g_tok[e*Cn + gr];
#pragma unroll
            for (int nt = 0; nt < 8; nt++) {
                float c0 = acc[mt][nt][half*2+0];
                float c1 = acc[mt][nt][half*2+1];
                int col = n0 + warp_n*64 + nt*8 + tig*2;
                if (MODE == 0) {
                    float2* p = (float2*)(g_hs + (size_t)gr*(2*F2n) + (size_t)e*F2n + col);
                    *p = make_float2(c0, c1);
                } else if (MODE == 1) {
                    float2* p = (float2*)(g_hs + (size_t)gr*(2*F2n) + (size_t)e*F2n + col);
                    float2 g = *p;
                    *p = make_float2(fmaxf(g.x, 0.f)*c0, fmaxf(g.y, 0.f)*c1);
                } else if (MODE == 2) {
                    if (ok) {
                        float2* p = (float2*)(g_hbuf + ((size_t)e*Cn + gr)*Fn + col);
                        *p = make_float2(c0, c1);
                    }
                } else if (MODE == 3) {
                    if (ok) {
                        float2* p = (float2*)(g_hbuf + ((size_t)e*Cn + gr)*Fn + col);
                        float2 g = *p;
                        *p = make_float2(fmaxf(g.x, 0.f)*c0*w, fmaxf(g.y, 0.f)*c1*w);
                    }
                } else if (MODE == 4) {
                    float2* p = (float2*)(out + (size_t)gr*Hn + col);
                    *p = make_float2(c0, c1);
                } else {
                    if (ok) {
                        float* p = out + (size_t)tok*Hn + col;
                        atomicAdd(p + 0, c0);
                        atomicAdd(p + 1, c1);
                    }
                }
            }
        }
    }
#undef LDA
#undef LDBV
#undef STO
}

// ---------------- launch ----------------
extern "C" void kernel_launch(void* const* d_in, const int* in_sizes, int n_in,
                              void* d_out, int out_size) {
    const float* x   = (const float*)d_in[0];
    const float* rw  = (const float*)d_in[1];
    const float* wg  = (const float*)d_in[2];
    const float* wu  = (const float*)d_in[3];
    const float* wd  = (const float*)d_in[4];
    const float* swg = (const float*)d_in[5];
    const float* swu = (const float*)d_in[6];
    const float* swd = (const float*)d_in[7];
    float* out = (float*)d_out;

    cudaFuncSetAttribute(mm_s<0>, cudaFuncAttributeMaxDynamicSharedMemorySize, SMB);
    cudaFuncSetAttribute(mm_s<1>, cudaFuncAttributeMaxDynamicSharedMemorySize, SMB);
    cudaFuncSetAttribute(mm_s<2>, cudaFuncAttributeMaxDynamicSharedMemorySize, SMB);
    cudaFuncSetAttribute(mm_s<3>, cudaFuncAttributeMaxDynamicSharedMemorySize, SMB);
    cudaFuncSetAttribute(mm_s<4>, cudaFuncAttributeMaxDynamicSharedMemorySize, SMB);
    cudaFuncSetAttribute(mm_s<5>, cudaFuncAttributeMaxDynamicSharedMemorySize, SMB);

    zero_kernel<<<1, 64>>>();
    logits_kernel<<<dim3(En/64, Tn/64), 256>>>(x, rw);
    router_post_kernel<<<Tn, 64>>>();
    hist_kernel<<<NCHUNK, CHSZ>>>();
    scan_kernel<<<1, En>>>();
    pos_kernel<<<NCHUNK, CHSZ>>>();

    // shared gate -> shared up (fuses relu(g)*u into g_hs)
    mm_s<0><<<dim3(F2n/128, Tn/128, 2), 256, SMB>>>(x, swg, out);
    mm_s<1><<<dim3(F2n/128, Tn/128, 2), 256, SMB>>>(x, swu, out);
    // expert gate -> expert up (fuses relu(g)*u*w into g_hbuf)
    mm_s<2><<<dim3(Fn/128, (Cn+127)/128, En), 256, SMB>>>(x, wg, out);
    mm_s<3><<<dim3(Fn/128, (Cn+127)/128, En), 256, SMB>>>(x, wu, out);
    // shared down initializes out; expert down accumulates
    mm_s<4><<<dim3(Hn/128, Tn/128, 1), 256, SMB>>>(x, swd, out);
    mm_s<5><<<dim3(Hn/128, (Cn+127)/128, En), 256, SMB>>>(x, wd, out);

    int write_aux = (out_size > Tn*Hn) ? 1 : 0;
    aux_kernel<<<1, En>>>(out, write_aux);
}